// round 13
// baseline (speedup 1.0000x reference)
#include <cuda_runtime.h>
#include <cuda_bf16.h>
#include <math.h>
#include <stdint.h>

#define NPTS 4096
#define DIM  512
#define KPK  1536              // packed K = [512 | 512 | 512]
#define BK   64
#define NSTAGE (KPK / BK)      // 24
#define SSTRIDE 32768          // per-stage smem (A 16KB + B 16KB)
#define BIGF   1e30f
#define INFKEY 0xFFFFFFFFFFFFFFFFull
#define TRANS_LD 132

// ---------------- scratch (static device globals; no allocation) ----------------
__device__ float g_dist[2][(size_t)NPTS * NPTS];            // 2 x 64MB distance matrices
__device__ __nv_bfloat16 g_pkA[2][(size_t)NPTS * KPK];      // [hi | lo | hi]
__device__ __nv_bfloat16 g_pkB[2][(size_t)NPTS * KPK];      // [hi | hi | lo]
__device__ float g_sq[2][NPTS];                             // squared norms (fp32)
__device__ float g_rowdiff[NPTS];                           // per-row (x1-x2)^2 sums
__device__ float g_deaths[2][NPTS];                         // slot-based deaths (root id = slot)
__device__ int   g_comp[2][NPTS];                           // Boruvka component labels
__device__ unsigned long long g_lanebest[2][NPTS][32];      // per-lane cached min outgoing
__device__ unsigned long long g_rowbest[2][NPTS];           // per-row best outgoing edge key
__device__ int   g_done[2];
__device__ int   g_sortcnt;                                 // sort-block arrival counter

// ---------------- helpers ----------------
__device__ __forceinline__ uint32_t smem_u32(const void* p) {
    uint32_t a;
    asm("{ .reg .u64 t; cvta.to.shared.u64 t, %1; cvt.u32.u64 %0, t; }" : "=r"(a) : "l"(p));
    return a;
}
__device__ __forceinline__ uint32_t swz(uint32_t b) { return b ^ ((b >> 3) & 0x70); }

__device__ __forceinline__ void cp16(uint32_t s, const void* g) {
    asm volatile("cp.async.cg.shared.global [%0], [%1], 16;" :: "r"(s), "l"(g));
}
__device__ __forceinline__ void ldsm4(uint32_t& r0, uint32_t& r1, uint32_t& r2, uint32_t& r3,
                                      uint32_t a) {
    asm volatile("ldmatrix.sync.aligned.m8n8.x4.shared.b16 {%0,%1,%2,%3}, [%4];"
                 : "=r"(r0), "=r"(r1), "=r"(r2), "=r"(r3) : "r"(a));
}
__device__ __forceinline__ void mma16816(float* c, const uint32_t* a, const uint32_t* b) {
    asm volatile("mma.sync.aligned.m16n8k16.row.col.f32.bf16.bf16.f32 "
                 "{%0,%1,%2,%3}, {%4,%5,%6,%7}, {%8,%9}, {%0,%1,%2,%3};"
                 : "+f"(c[0]), "+f"(c[1]), "+f"(c[2]), "+f"(c[3])
                 : "r"(a[0]), "r"(a[1]), "r"(a[2]), "r"(a[3]), "r"(b[0]), "r"(b[1]));
}

// ---------------- prep: hi/lo operands + sq norms + L2-diff + ALL init (warp/row) ----------------
__global__ void prep_kernel(const float* __restrict__ x1, const float* __restrict__ x2) {
    int w    = (blockIdx.x * 256 + threadIdx.x) >> 5;   // 0..8191
    int lane = threadIdx.x & 31;
    int mat  = w >> 12;
    int row  = w & (NPTS - 1);
    const float* p = (mat ? x2 : x1) + (size_t)row * DIM;
    const float* q = x2 + (size_t)row * DIM;
    __nv_bfloat16* pa = g_pkA[mat] + (size_t)row * KPK;
    __nv_bfloat16* pb = g_pkB[mat] + (size_t)row * KPK;
    float s = 0.f, sd = 0.f;
    for (int c = lane * 4; c < DIM; c += 128) {
        float4 v = *(const float4*)(p + c);
        __nv_bfloat16 h0 = __float2bfloat16(v.x), h1 = __float2bfloat16(v.y);
        __nv_bfloat16 h2 = __float2bfloat16(v.z), h3 = __float2bfloat16(v.w);
        __nv_bfloat16 l0 = __float2bfloat16(v.x - __bfloat162float(h0));
        __nv_bfloat16 l1 = __float2bfloat16(v.y - __bfloat162float(h1));
        __nv_bfloat16 l2 = __float2bfloat16(v.z - __bfloat162float(h2));
        __nv_bfloat16 l3 = __float2bfloat16(v.w - __bfloat162float(h3));
        ushort4 hs = make_ushort4(__bfloat16_as_ushort(h0), __bfloat16_as_ushort(h1),
                                  __bfloat16_as_ushort(h2), __bfloat16_as_ushort(h3));
        ushort4 ls = make_ushort4(__bfloat16_as_ushort(l0), __bfloat16_as_ushort(l1),
                                  __bfloat16_as_ushort(l2), __bfloat16_as_ushort(l3));
        *(ushort4*)(pa + c)        = hs;   // A: [hi | lo | hi]
        *(ushort4*)(pa + 512 + c)  = ls;
        *(ushort4*)(pa + 1024 + c) = hs;
        *(ushort4*)(pb + c)        = hs;   // B: [hi | hi | lo]
        *(ushort4*)(pb + 512 + c)  = hs;
        *(ushort4*)(pb + 1024 + c) = ls;
        s += v.x * v.x + v.y * v.y + v.z * v.z + v.w * v.w;
        if (mat == 0) {
            float4 u = *(const float4*)(q + c);
            float d0 = v.x - u.x, d1 = v.y - u.y, d2 = v.z - u.z, d3 = v.w - u.w;
            sd += d0 * d0 + d1 * d1 + d2 * d2 + d3 * d3;
        }
    }
    #pragma unroll
    for (int o = 16; o > 0; o >>= 1) {
        s  += __shfl_xor_sync(0xffffffffu, s, o);
        sd += __shfl_xor_sync(0xffffffffu, sd, o);
    }
    // fused init
    g_lanebest[mat][row][lane] = 0ull;   // 0 = "must scan" sentinel
    if (lane == 0) {
        g_sq[mat][row] = s;
        if (mat == 0) g_rowdiff[row] = sd;
        g_comp[mat][row] = row;
        g_rowbest[mat][row] = INFKEY;
        g_deaths[mat][row] = 0.0f;       // slot-based recording; root slot stays 0
    }
    if (w == 0) {
        if (lane < 2) g_done[lane] = 0;
        if (lane == 0) g_sortcnt = 0;
    }
}

// ---------------- distance matrix: mma.sync bf16 GEMM, M128 N128 K1536 ----------------
// 8 warps (4m x 2n), warp tile 32x64, BK=64, 3-stage cp.async pipeline, ONE sync/stage.
__global__ void __launch_bounds__(256, 2) dist_hmma_kernel() {
    extern __shared__ __align__(128) unsigned char sraw[];   // 98304 B (3 stages)
    int mat = blockIdx.z;
    int t = blockIdx.x, bi = 0, len = 32;
    while (t >= len) { t -= len; len--; bi++; }
    int bj = bi + t;

    const __nv_bfloat16* pkA = g_pkA[mat];
    const __nv_bfloat16* pkB = g_pkB[mat];
    float* Dst = g_dist[mat];
    int tid = threadIdx.x, lane = tid & 31, wid = tid >> 5;
    int wm = wid & 3, wn = wid >> 2;           // warp tile: rows wm*32, cols wn*64
    uint32_t sb = smem_u32(sraw);

    float acc[2][8][4];
    #pragma unroll
    for (int im = 0; im < 2; im++)
        #pragma unroll
        for (int in = 0; in < 8; in++)
            #pragma unroll
            for (int q = 0; q < 4; q++) acc[im][in][q] = 0.f;

    int rowA0 = bi * 128, rowB0 = bj * 128;
    // stage b = s % 3: A at b*SSTRIDE, B at b*SSTRIDE + 16384
    #define ISSUE(s) do {                                                           \
        int _b = (s) % 3; int _k0 = (s) * BK;                                       \
        _Pragma("unroll")                                                           \
        for (int _h = 0; _h < 4; _h++) {                                            \
            int _tt = tid + _h * 256;                                               \
            int _row = _tt >> 3, _c16 = _tt & 7;                                    \
            uint32_t _so = swz((uint32_t)(_row * 128 + _c16 * 16));                 \
            cp16(sb + _b * SSTRIDE + _so,                                           \
                 pkA + (size_t)(rowA0 + _row) * KPK + _k0 + _c16 * 8);              \
            cp16(sb + _b * SSTRIDE + 16384 + _so,                                   \
                 pkB + (size_t)(rowB0 + _row) * KPK + _k0 + _c16 * 8);              \
        }                                                                           \
        asm volatile("cp.async.commit_group;" ::: "memory");                        \
    } while (0)

    ISSUE(0); ISSUE(1);
    for (int s = 0; s < NSTAGE; s++) {
        if (s < NSTAGE - 1) asm volatile("cp.async.wait_group 1;" ::: "memory");
        else                asm volatile("cp.async.wait_group 0;" ::: "memory");
        __syncthreads();
        if (s + 2 < NSTAGE) ISSUE(s + 2);     // writes buffer (s-1)%3: consumed last iter
        uint32_t baseA = sb + (s % 3) * SSTRIDE;
        uint32_t baseB = baseA + 16384;
        #pragma unroll
        for (int kk = 0; kk < 4; kk++) {
            uint32_t a[2][4], bb[8][2];
            #pragma unroll
            for (int im = 0; im < 2; im++) {
                uint32_t addr = baseA + swz((uint32_t)((wm * 32 + im * 16 + (lane & 15)) * 128
                                                       + kk * 32 + (lane >> 4) * 16));
                ldsm4(a[im][0], a[im][1], a[im][2], a[im][3], addr);
            }
            #pragma unroll
            for (int np = 0; np < 4; np++) {
                uint32_t addr = baseB + swz((uint32_t)((wn * 64 + np * 16 + ((lane >> 4) << 3)
                                                        + (lane & 7)) * 128
                                                       + kk * 32 + ((lane >> 3) & 1) * 16));
                uint32_t r0, r1, r2, r3;
                ldsm4(r0, r1, r2, r3, addr);
                bb[np * 2][0] = r0; bb[np * 2][1] = r1;
                bb[np * 2 + 1][0] = r2; bb[np * 2 + 1][1] = r3;
            }
            #pragma unroll
            for (int im = 0; im < 2; im++)
                #pragma unroll
                for (int in = 0; in < 8; in++)
                    mma16816(acc[im][in], a[im], bb[in]);
        }
    }
    #undef ISSUE

    // ---- epilogue: dist transform + row-major stores ----
    bool diag = (bi == bj);
    int giBase = bi * 128, gjBase = bj * 128;
    float sqr[2][2], sqc[8][2];
    #pragma unroll
    for (int im = 0; im < 2; im++)
        #pragma unroll
        for (int p = 0; p < 2; p++)
            sqr[im][p] = g_sq[mat][giBase + wm * 32 + im * 16 + (lane >> 2) + p * 8];
    #pragma unroll
    for (int in = 0; in < 8; in++) {
        int col = gjBase + wn * 64 + in * 8 + (lane & 3) * 2;
        sqc[in][0] = g_sq[mat][col];
        sqc[in][1] = g_sq[mat][col + 1];
    }
    #pragma unroll
    for (int im = 0; im < 2; im++) {
        #pragma unroll
        for (int in = 0; in < 8; in++) {
            #pragma unroll
            for (int p = 0; p < 2; p++) {
                int m = giBase + wm * 32 + im * 16 + (lane >> 2) + p * 8;
                int n = gjBase + wn * 64 + in * 8 + (lane & 3) * 2;
                float d0 = sqr[im][p] + sqc[in][0] - 2.f * acc[im][in][p * 2];
                float d1 = sqr[im][p] + sqc[in][1] - 2.f * acc[im][in][p * 2 + 1];
                d0 = sqrtf(fmaxf(d0, 1e-12f));
                d1 = sqrtf(fmaxf(d1, 1e-12f));
                if (diag) { if (m == n) d0 = BIGF; if (m == n + 1) d1 = BIGF; }
                acc[im][in][p * 2]     = d0;
                acc[im][in][p * 2 + 1] = d1;
                *(float2*)(Dst + (size_t)m * NPTS + n) = make_float2(d0, d1);
            }
        }
    }

    // ---- mirror via smem transpose (two 64-col chunks; 64 rows x 4 segs of 32) ----
    if (!diag) {
        float* trans = (float*)sraw;
        #pragma unroll
        for (int h = 0; h < 2; h++) {
            __syncthreads();
            if (wn == h) {
                #pragma unroll
                for (int im = 0; im < 2; im++)
                    #pragma unroll
                    for (int in = 0; in < 8; in++)
                        #pragma unroll
                        for (int p = 0; p < 2; p++) {
                            int ml = wm * 32 + im * 16 + (lane >> 2) + p * 8;
                            int nl = in * 8 + (lane & 3) * 2;
                            trans[nl * TRANS_LD + ml]       = acc[im][in][p * 2];
                            trans[(nl + 1) * TRANS_LD + ml] = acc[im][in][p * 2 + 1];
                        }
            }
            __syncthreads();
            int r = tid >> 2, seg = tid & 3;
            const float* srcp = trans + r * TRANS_LD + seg * 32;
            float* dstp = Dst + (size_t)(gjBase + h * 64 + r) * NPTS + giBase + seg * 32;
            #pragma unroll
            for (int i = 0; i < 8; i++)
                *(float4*)(dstp + i * 4) = *(const float4*)(srcp + i * 4);
        }
    }
}

// ---------------- Boruvka scan: warp/row, per-lane exact cache, unrolled for MLP ----------------
__global__ void __launch_bounds__(256) boruvka_scan() {
    int w    = (blockIdx.x * 256 + threadIdx.x) >> 5;   // 0..8191
    int lane = threadIdx.x & 31;
    int mat  = w >> 12;
    int row  = w & (NPTS - 1);
    if (g_done[mat]) return;

    int myc = g_comp[mat][row];
    unsigned long long lk = g_lanebest[mat][row][lane];

    bool need = (lk == 0ull);
    if (!need && lk != INFKEY) {
        int eid = (int)(lk & 0xFFFFFF);
        int u = eid >> 12, v = eid & (NPTS - 1);
        int other = (u == row) ? v : u;
        need = (g_comp[mat][other] == myc);
    }
    if (need) {
        const float4* drow = (const float4*)(g_dist[mat] + (size_t)row * NPTS);
        const int4*   crow = (const int4*)(g_comp[mat]);
        int rowsh = row << 12;
        unsigned long long best = INFKEY;
        #pragma unroll 4
        for (int t = lane; t < NPTS / 4; t += 32) {
            float4 d = drow[t];
            int4   c = crow[t];
            int k = t * 4;
            if (c.x != myc) {
                int id = (k < row) ? ((k << 12) | row) : (rowsh | k);
                best = min(best, ((unsigned long long)__float_as_uint(d.x) << 24)
                                 | (unsigned long long)id);
            }
            if (c.y != myc) {
                int k1 = k + 1;
                int id = (k1 < row) ? ((k1 << 12) | row) : (rowsh | k1);
                best = min(best, ((unsigned long long)__float_as_uint(d.y) << 24)
                                 | (unsigned long long)id);
            }
            if (c.z != myc) {
                int k2 = k + 2;
                int id = (k2 < row) ? ((k2 << 12) | row) : (rowsh | k2);
                best = min(best, ((unsigned long long)__float_as_uint(d.z) << 24)
                                 | (unsigned long long)id);
            }
            if (c.w != myc) {
                int k3 = k + 3;
                int id = (k3 < row) ? ((k3 << 12) | row) : (rowsh | k3);
                best = min(best, ((unsigned long long)__float_as_uint(d.w) << 24)
                                 | (unsigned long long)id);
            }
        }
        lk = best;
        g_lanebest[mat][row][lane] = lk;
    }
    __syncwarp(0xffffffffu);
    unsigned long long rb = lk;
    #pragma unroll
    for (int o = 16; o > 0; o >>= 1) {
        unsigned long long other = __shfl_xor_sync(0xffffffffu, rb, o);
        rb = min(rb, other);
    }
    if (lane == 0) g_rowbest[mat][row] = rb;
}

// ---------------- Boruvka merge: one block per matrix, atomic-free death slots ----------------
__global__ void __launch_bounds__(1024) boruvka_merge() {
    int mat = blockIdx.x;
    if (g_done[mat]) return;

    __shared__ unsigned long long sbest[NPTS];   // 32KB
    __shared__ unsigned short    par[NPTS];      // 8KB
    __shared__ int s_roots;

    int tid = threadIdx.x;
    #pragma unroll 4
    for (int c = tid; c < NPTS; c += 1024) sbest[c] = INFKEY;
    __syncthreads();

    #pragma unroll 4
    for (int r = tid; r < NPTS; r += 1024) {
        unsigned long long k = g_rowbest[mat][r];
        if (k != INFKEY) atomicMin(&sbest[g_comp[mat][r]], k);
    }
    __syncthreads();

    // hook + slot-based death record: dying root c writes g_deaths[mat][c]
    #pragma unroll 4
    for (int c = tid; c < NPTS; c += 1024) {
        unsigned long long k = sbest[c];
        int p = c;
        if (k != INFKEY) {
            int eid = (int)(k & 0xFFFFFF);
            int u = eid >> 12, v = eid & (NPTS - 1);
            int cu = g_comp[mat][u];
            int d = (cu == c) ? g_comp[mat][v] : cu;
            p = d;
            bool mutual = (sbest[d] == k);
            if (!(mutual && c < d))            // survivor (mutual smaller) skips
                g_deaths[mat][c] = __uint_as_float((unsigned)(k >> 24));
        }
        par[c] = (unsigned short)p;
    }
    __syncthreads();

    #pragma unroll 4
    for (int c = tid; c < NPTS; c += 1024) {
        int p = par[c];
        if (p != c && par[p] == c && c < p) par[c] = (unsigned short)c;
    }
    __syncthreads();

    for (int it = 0; it < 12; it++) {
        int changed = 0;
        #pragma unroll 4
        for (int c = tid; c < NPTS; c += 1024) {
            int p = par[c];
            int gp = par[p];
            if (gp != p) { par[c] = (unsigned short)gp; changed = 1; }
        }
        if (!__syncthreads_or(changed)) break;
    }

    if (tid == 0) s_roots = 0;
    __syncthreads();
    int rootcnt = 0;
    #pragma unroll 4
    for (int i = tid; i < NPTS; i += 1024) {
        int nc = par[g_comp[mat][i]];
        g_comp[mat][i] = nc;
        rootcnt += (nc == i);
    }
    #pragma unroll
    for (int o = 16; o > 0; o >>= 1) rootcnt += __shfl_xor_sync(0xffffffffu, rootcnt, o);
    if ((tid & 31) == 0 && rootcnt) atomicAdd(&s_roots, rootcnt);
    __syncthreads();
    if (tid == 0 && s_roots <= 1) g_done[mat] = 1;
}

// ---------------- bitonic sort (warp-local low phases) + fused final loss ----------------
__global__ void __launch_bounds__(1024) sort_kernel(float* __restrict__ out) {
    int mat = blockIdx.x;
    __shared__ float s[NPTS];
    __shared__ float red[1024];
    __shared__ int s_last;
    int tid = threadIdx.x;

    for (int i = tid; i < NPTS; i += 1024)
        s[i] = g_deaths[mat][i];             // 4095 deaths + one 0 (surviving root's slot)
    __syncthreads();
    for (int k = 2; k <= NPTS; k <<= 1)
        for (int j2 = k >> 1; j2 > 0; j2 >>= 1) {
            for (int i = tid; i < NPTS; i += 1024) {
                int ixj = i ^ j2;
                if (ixj > i) {
                    float a = s[i], b = s[ixj];
                    bool up = ((i & k) == 0);
                    if ((a > b) == up) { s[i] = b; s[ixj] = a; }
                }
            }
            int next = (j2 > 1) ? (j2 >> 1) : k;   // k-boundary: next distance is k
            if (next >= 32) __syncthreads();
            else            __syncwarp(0xffffffffu);
        }
    __syncthreads();
    for (int i = tid; i < NPTS; i += 1024)
        g_deaths[mat][i] = s[i];

    // ---- last sorted block computes the final loss ----
    __threadfence();
    __syncthreads();
    if (tid == 0) s_last = (atomicAdd(&g_sortcnt, 1) == 1);
    __syncthreads();
    if (!s_last) return;
    __threadfence();
    const float inv = 1.0f / ((float)NPTS * (float)DIM);
    float acc = 0.f;
    for (int i = tid; i < NPTS; i += 1024) {
        float a = g_deaths[0][i], b = g_deaths[1][i];
        acc += fminf(fabsf(a - b), 0.5f * (a + b));
        acc += g_rowdiff[i] * inv;
    }
    red[tid] = acc; __syncthreads();
    #pragma unroll
    for (int st = 512; st > 0; st >>= 1) {
        if (tid < st) red[tid] += red[tid + st];
        __syncthreads();
    }
    if (tid == 0) out[0] = red[0];
}

extern "C" void kernel_launch(void* const* d_in, const int* in_sizes, int n_in,
                              void* d_out, int out_size) {
    const float* x1 = (const float*)d_in[0];
    const float* x2 = (const float*)d_in[1];
    float* out = (float*)d_out;

    cudaFuncSetAttribute(dist_hmma_kernel, cudaFuncAttributeMaxDynamicSharedMemorySize, 98304);

    prep_kernel<<<1024, 256>>>(x1, x2);
    dist_hmma_kernel<<<dim3(528, 1, 2), 256, 98304>>>();
    for (int r = 0; r < 12; r++) {
        boruvka_scan <<<1024, 256>>>();
        boruvka_merge<<<2, 1024>>>();
    }
    sort_kernel<<<2, 1024>>>(out);
}

// round 14
// speedup vs baseline: 1.0437x; 1.0437x over previous
#include <cuda_runtime.h>
#include <cuda_bf16.h>
#include <math.h>
#include <stdint.h>

#define NPTS 4096
#define DIM  512
#define KPK  1536              // packed K = [512 | 512 | 512]
#define BK   64
#define NSTAGE (KPK / BK)      // 24
#define BIGF   1e30f
#define INFKEY 0xFFFFFFFFFFFFFFFFull
#define TRANS_LD 132

// ---------------- scratch (static device globals; no allocation) ----------------
__device__ float g_dist[2][(size_t)NPTS * NPTS];            // 2 x 64MB distance matrices
__device__ __nv_bfloat16 g_pkA[2][(size_t)NPTS * KPK];      // [hi | lo | hi]
__device__ __nv_bfloat16 g_pkB[2][(size_t)NPTS * KPK];      // [hi | hi | lo]
__device__ float g_sq[2][NPTS];                             // squared norms (fp32)
__device__ float g_rowdiff[NPTS];                           // per-row (x1-x2)^2 sums
__device__ float g_deaths[2][NPTS];                         // slot-based deaths (root id = slot)
__device__ int   g_comp[2][NPTS];                           // Boruvka component labels
__device__ unsigned long long g_lanebest[2][NPTS][32];      // per-lane cached min outgoing
__device__ unsigned long long g_rowbest[2][NPTS];           // per-row best outgoing edge key
__device__ int   g_done[2];
__device__ int   g_sortcnt;                                 // sort-block arrival counter

// ---------------- helpers ----------------
__device__ __forceinline__ uint32_t smem_u32(const void* p) {
    uint32_t a;
    asm("{ .reg .u64 t; cvta.to.shared.u64 t, %1; cvt.u32.u64 %0, t; }" : "=r"(a) : "l"(p));
    return a;
}
__device__ __forceinline__ uint32_t swz(uint32_t b) { return b ^ ((b >> 3) & 0x70); }

__device__ __forceinline__ void cp16(uint32_t s, const void* g) {
    asm volatile("cp.async.cg.shared.global [%0], [%1], 16;" :: "r"(s), "l"(g));
}
__device__ __forceinline__ void ldsm4(uint32_t& r0, uint32_t& r1, uint32_t& r2, uint32_t& r3,
                                      uint32_t a) {
    asm volatile("ldmatrix.sync.aligned.m8n8.x4.shared.b16 {%0,%1,%2,%3}, [%4];"
                 : "=r"(r0), "=r"(r1), "=r"(r2), "=r"(r3) : "r"(a));
}
__device__ __forceinline__ void mma16816(float* c, const uint32_t* a, const uint32_t* b) {
    asm volatile("mma.sync.aligned.m16n8k16.row.col.f32.bf16.bf16.f32 "
                 "{%0,%1,%2,%3}, {%4,%5,%6,%7}, {%8,%9}, {%0,%1,%2,%3};"
                 : "+f"(c[0]), "+f"(c[1]), "+f"(c[2]), "+f"(c[3])
                 : "r"(a[0]), "r"(a[1]), "r"(a[2]), "r"(a[3]), "r"(b[0]), "r"(b[1]));
}

// ---------------- prep: hi/lo operands + sq norms + L2-diff + ALL init (warp/row) ----------------
__global__ void prep_kernel(const float* __restrict__ x1, const float* __restrict__ x2) {
    int w    = (blockIdx.x * 256 + threadIdx.x) >> 5;   // 0..8191
    int lane = threadIdx.x & 31;
    int mat  = w >> 12;
    int row  = w & (NPTS - 1);
    const float* p = (mat ? x2 : x1) + (size_t)row * DIM;
    const float* q = x2 + (size_t)row * DIM;
    __nv_bfloat16* pa = g_pkA[mat] + (size_t)row * KPK;
    __nv_bfloat16* pb = g_pkB[mat] + (size_t)row * KPK;
    float s = 0.f, sd = 0.f;
    for (int c = lane * 4; c < DIM; c += 128) {
        float4 v = *(const float4*)(p + c);
        __nv_bfloat16 h0 = __float2bfloat16(v.x), h1 = __float2bfloat16(v.y);
        __nv_bfloat16 h2 = __float2bfloat16(v.z), h3 = __float2bfloat16(v.w);
        __nv_bfloat16 l0 = __float2bfloat16(v.x - __bfloat162float(h0));
        __nv_bfloat16 l1 = __float2bfloat16(v.y - __bfloat162float(h1));
        __nv_bfloat16 l2 = __float2bfloat16(v.z - __bfloat162float(h2));
        __nv_bfloat16 l3 = __float2bfloat16(v.w - __bfloat162float(h3));
        ushort4 hs = make_ushort4(__bfloat16_as_ushort(h0), __bfloat16_as_ushort(h1),
                                  __bfloat16_as_ushort(h2), __bfloat16_as_ushort(h3));
        ushort4 ls = make_ushort4(__bfloat16_as_ushort(l0), __bfloat16_as_ushort(l1),
                                  __bfloat16_as_ushort(l2), __bfloat16_as_ushort(l3));
        *(ushort4*)(pa + c)        = hs;   // A: [hi | lo | hi]
        *(ushort4*)(pa + 512 + c)  = ls;
        *(ushort4*)(pa + 1024 + c) = hs;
        *(ushort4*)(pb + c)        = hs;   // B: [hi | hi | lo]
        *(ushort4*)(pb + 512 + c)  = hs;
        *(ushort4*)(pb + 1024 + c) = ls;
        s += v.x * v.x + v.y * v.y + v.z * v.z + v.w * v.w;
        if (mat == 0) {
            float4 u = *(const float4*)(q + c);
            float d0 = v.x - u.x, d1 = v.y - u.y, d2 = v.z - u.z, d3 = v.w - u.w;
            sd += d0 * d0 + d1 * d1 + d2 * d2 + d3 * d3;
        }
    }
    #pragma unroll
    for (int o = 16; o > 0; o >>= 1) {
        s  += __shfl_xor_sync(0xffffffffu, s, o);
        sd += __shfl_xor_sync(0xffffffffu, sd, o);
    }
    // fused init
    g_lanebest[mat][row][lane] = 0ull;   // 0 = "must scan" sentinel
    if (lane == 0) {
        g_sq[mat][row] = s;
        if (mat == 0) g_rowdiff[row] = sd;
        g_comp[mat][row] = row;
        g_rowbest[mat][row] = INFKEY;
        g_deaths[mat][row] = 0.0f;       // slot-based recording; root slot stays 0
    }
    if (w == 0) {
        if (lane < 2) g_done[lane] = 0;
        if (lane == 0) g_sortcnt = 0;
    }
}

// ---------------- distance matrix: mma.sync bf16 GEMM, M128 N128 K1536 (R8/R12 config) ----------------
// 8 warps (4m x 2n), warp tile 32x64, BK=64 (128B rows, conflict-free ldmatrix), 2-stage.
__global__ void __launch_bounds__(256, 2) dist_hmma_kernel() {
    extern __shared__ __align__(128) unsigned char sraw[];
    int mat = blockIdx.z;
    int t = blockIdx.x, bi = 0, len = 32;
    while (t >= len) { t -= len; len--; bi++; }
    int bj = bi + t;

    const __nv_bfloat16* pkA = g_pkA[mat];
    const __nv_bfloat16* pkB = g_pkB[mat];
    float* Dst = g_dist[mat];
    int tid = threadIdx.x, lane = tid & 31, wid = tid >> 5;
    int wm = wid & 3, wn = wid >> 2;           // warp tile: rows wm*32, cols wn*64
    uint32_t sb = smem_u32(sraw);

    float acc[2][8][4];
    #pragma unroll
    for (int im = 0; im < 2; im++)
        #pragma unroll
        for (int in = 0; in < 8; in++)
            #pragma unroll
            for (int q = 0; q < 4; q++) acc[im][in][q] = 0.f;

    int rowA0 = bi * 128, rowB0 = bj * 128;
    #define ISSUE(s) do {                                                           \
        int _b = (s) & 1; int _k0 = (s) * BK;                                       \
        _Pragma("unroll")                                                           \
        for (int _h = 0; _h < 4; _h++) {                                            \
            int _tt = tid + _h * 256;                                               \
            int _row = _tt >> 3, _c16 = _tt & 7;                                    \
            uint32_t _so = swz((uint32_t)(_row * 128 + _c16 * 16));                 \
            cp16(sb + _b * 16384 + _so,                                             \
                 pkA + (size_t)(rowA0 + _row) * KPK + _k0 + _c16 * 8);              \
            cp16(sb + 32768 + _b * 16384 + _so,                                     \
                 pkB + (size_t)(rowB0 + _row) * KPK + _k0 + _c16 * 8);              \
        }                                                                           \
        asm volatile("cp.async.commit_group;" ::: "memory");                        \
    } while (0)

    ISSUE(0);
    for (int s = 0; s < NSTAGE; s++) {
        if (s < NSTAGE - 1) { ISSUE(s + 1); asm volatile("cp.async.wait_group 1;" ::: "memory"); }
        else                {               asm volatile("cp.async.wait_group 0;" ::: "memory"); }
        __syncthreads();
        uint32_t baseA = sb + (s & 1) * 16384;
        uint32_t baseB = sb + 32768 + (s & 1) * 16384;
        #pragma unroll
        for (int kk = 0; kk < 4; kk++) {
            uint32_t a[2][4], bb[8][2];
            #pragma unroll
            for (int im = 0; im < 2; im++) {
                uint32_t addr = baseA + swz((uint32_t)((wm * 32 + im * 16 + (lane & 15)) * 128
                                                       + kk * 32 + (lane >> 4) * 16));
                ldsm4(a[im][0], a[im][1], a[im][2], a[im][3], addr);
            }
            #pragma unroll
            for (int np = 0; np < 4; np++) {
                uint32_t addr = baseB + swz((uint32_t)((wn * 64 + np * 16 + ((lane >> 4) << 3)
                                                        + (lane & 7)) * 128
                                                       + kk * 32 + ((lane >> 3) & 1) * 16));
                uint32_t r0, r1, r2, r3;
                ldsm4(r0, r1, r2, r3, addr);
                bb[np * 2][0] = r0; bb[np * 2][1] = r1;
                bb[np * 2 + 1][0] = r2; bb[np * 2 + 1][1] = r3;
            }
            #pragma unroll
            for (int im = 0; im < 2; im++)
                #pragma unroll
                for (int in = 0; in < 8; in++)
                    mma16816(acc[im][in], a[im], bb[in]);
        }
        __syncthreads();
    }
    #undef ISSUE

    // ---- epilogue: dist transform + row-major stores ----
    bool diag = (bi == bj);
    int giBase = bi * 128, gjBase = bj * 128;
    float sqr[2][2], sqc[8][2];
    #pragma unroll
    for (int im = 0; im < 2; im++)
        #pragma unroll
        for (int p = 0; p < 2; p++)
            sqr[im][p] = g_sq[mat][giBase + wm * 32 + im * 16 + (lane >> 2) + p * 8];
    #pragma unroll
    for (int in = 0; in < 8; in++) {
        int col = gjBase + wn * 64 + in * 8 + (lane & 3) * 2;
        sqc[in][0] = g_sq[mat][col];
        sqc[in][1] = g_sq[mat][col + 1];
    }
    #pragma unroll
    for (int im = 0; im < 2; im++) {
        #pragma unroll
        for (int in = 0; in < 8; in++) {
            #pragma unroll
            for (int p = 0; p < 2; p++) {
                int m = giBase + wm * 32 + im * 16 + (lane >> 2) + p * 8;
                int n = gjBase + wn * 64 + in * 8 + (lane & 3) * 2;
                float d0 = sqr[im][p] + sqc[in][0] - 2.f * acc[im][in][p * 2];
                float d1 = sqr[im][p] + sqc[in][1] - 2.f * acc[im][in][p * 2 + 1];
                d0 = sqrtf(fmaxf(d0, 1e-12f));
                d1 = sqrtf(fmaxf(d1, 1e-12f));
                if (diag) { if (m == n) d0 = BIGF; if (m == n + 1) d1 = BIGF; }
                acc[im][in][p * 2]     = d0;
                acc[im][in][p * 2 + 1] = d1;
                *(float2*)(Dst + (size_t)m * NPTS + n) = make_float2(d0, d1);
            }
        }
    }

    // ---- mirror via smem transpose (two 64-col chunks; 64 rows x 4 segs of 32) ----
    if (!diag) {
        float* trans = (float*)sraw;
        #pragma unroll
        for (int h = 0; h < 2; h++) {
            __syncthreads();
            if (wn == h) {
                #pragma unroll
                for (int im = 0; im < 2; im++)
                    #pragma unroll
                    for (int in = 0; in < 8; in++)
                        #pragma unroll
                        for (int p = 0; p < 2; p++) {
                            int ml = wm * 32 + im * 16 + (lane >> 2) + p * 8;
                            int nl = in * 8 + (lane & 3) * 2;
                            trans[nl * TRANS_LD + ml]       = acc[im][in][p * 2];
                            trans[(nl + 1) * TRANS_LD + ml] = acc[im][in][p * 2 + 1];
                        }
            }
            __syncthreads();
            int r = tid >> 2, seg = tid & 3;
            const float* srcp = trans + r * TRANS_LD + seg * 32;
            float* dstp = Dst + (size_t)(gjBase + h * 64 + r) * NPTS + giBase + seg * 32;
            #pragma unroll
            for (int i = 0; i < 8; i++)
                *(float4*)(dstp + i * 4) = *(const float4*)(srcp + i * 4);
        }
    }
}

// ---------------- Boruvka scan: warp/row, per-lane exact cache (unroll in scan path only) ----------------
__global__ void __launch_bounds__(256) boruvka_scan() {
    int w    = (blockIdx.x * 256 + threadIdx.x) >> 5;   // 0..8191
    int lane = threadIdx.x & 31;
    int mat  = w >> 12;
    int row  = w & (NPTS - 1);
    if (g_done[mat]) return;

    int myc = g_comp[mat][row];
    unsigned long long lk = g_lanebest[mat][row][lane];

    bool need = (lk == 0ull);
    if (!need && lk != INFKEY) {
        int eid = (int)(lk & 0xFFFFFF);
        int u = eid >> 12, v = eid & (NPTS - 1);
        int other = (u == row) ? v : u;
        need = (g_comp[mat][other] == myc);
    }
    if (need) {
        const float4* drow = (const float4*)(g_dist[mat] + (size_t)row * NPTS);
        const int4*   crow = (const int4*)(g_comp[mat]);
        int rowsh = row << 12;
        unsigned long long best = INFKEY;
        #pragma unroll 4
        for (int t = lane; t < NPTS / 4; t += 32) {
            float4 d = drow[t];
            int4   c = crow[t];
            int k = t * 4;
            if (c.x != myc) {
                int id = (k < row) ? ((k << 12) | row) : (rowsh | k);
                best = min(best, ((unsigned long long)__float_as_uint(d.x) << 24)
                                 | (unsigned long long)id);
            }
            if (c.y != myc) {
                int k1 = k + 1;
                int id = (k1 < row) ? ((k1 << 12) | row) : (rowsh | k1);
                best = min(best, ((unsigned long long)__float_as_uint(d.y) << 24)
                                 | (unsigned long long)id);
            }
            if (c.z != myc) {
                int k2 = k + 2;
                int id = (k2 < row) ? ((k2 << 12) | row) : (rowsh | k2);
                best = min(best, ((unsigned long long)__float_as_uint(d.z) << 24)
                                 | (unsigned long long)id);
            }
            if (c.w != myc) {
                int k3 = k + 3;
                int id = (k3 < row) ? ((k3 << 12) | row) : (rowsh | k3);
                best = min(best, ((unsigned long long)__float_as_uint(d.w) << 24)
                                 | (unsigned long long)id);
            }
        }
        lk = best;
        g_lanebest[mat][row][lane] = lk;
    }
    __syncwarp(0xffffffffu);
    unsigned long long rb = lk;
    #pragma unroll
    for (int o = 16; o > 0; o >>= 1) {
        unsigned long long other = __shfl_xor_sync(0xffffffffu, rb, o);
        rb = min(rb, other);
    }
    if (lane == 0) g_rowbest[mat][row] = rb;
}

// ---------------- Boruvka merge: one block per matrix, atomic-free death slots ----------------
__global__ void __launch_bounds__(1024) boruvka_merge() {
    int mat = blockIdx.x;
    if (g_done[mat]) return;

    __shared__ unsigned long long sbest[NPTS];   // 32KB
    __shared__ unsigned short    par[NPTS];      // 8KB
    __shared__ int s_roots;

    int tid = threadIdx.x;
    #pragma unroll 4
    for (int c = tid; c < NPTS; c += 1024) sbest[c] = INFKEY;
    __syncthreads();

    #pragma unroll 4
    for (int r = tid; r < NPTS; r += 1024) {
        unsigned long long k = g_rowbest[mat][r];
        if (k != INFKEY) atomicMin(&sbest[g_comp[mat][r]], k);
    }
    __syncthreads();

    // hook + slot-based death record: dying root c writes g_deaths[mat][c]
    #pragma unroll 4
    for (int c = tid; c < NPTS; c += 1024) {
        unsigned long long k = sbest[c];
        int p = c;
        if (k != INFKEY) {
            int eid = (int)(k & 0xFFFFFF);
            int u = eid >> 12, v = eid & (NPTS - 1);
            int cu = g_comp[mat][u];
            int d = (cu == c) ? g_comp[mat][v] : cu;
            p = d;
            bool mutual = (sbest[d] == k);
            if (!(mutual && c < d))            // survivor (mutual smaller) skips
                g_deaths[mat][c] = __uint_as_float((unsigned)(k >> 24));
        }
        par[c] = (unsigned short)p;
    }
    __syncthreads();

    #pragma unroll 4
    for (int c = tid; c < NPTS; c += 1024) {
        int p = par[c];
        if (p != c && par[p] == c && c < p) par[c] = (unsigned short)c;
    }
    __syncthreads();

    for (int it = 0; it < 12; it++) {
        int changed = 0;
        #pragma unroll 4
        for (int c = tid; c < NPTS; c += 1024) {
            int p = par[c];
            int gp = par[p];
            if (gp != p) { par[c] = (unsigned short)gp; changed = 1; }
        }
        if (!__syncthreads_or(changed)) break;
    }

    if (tid == 0) s_roots = 0;
    __syncthreads();
    int rootcnt = 0;
    #pragma unroll 4
    for (int i = tid; i < NPTS; i += 1024) {
        int nc = par[g_comp[mat][i]];
        g_comp[mat][i] = nc;
        rootcnt += (nc == i);
    }
    #pragma unroll
    for (int o = 16; o > 0; o >>= 1) rootcnt += __shfl_xor_sync(0xffffffffu, rootcnt, o);
    if ((tid & 31) == 0 && rootcnt) atomicAdd(&s_roots, rootcnt);
    __syncthreads();
    if (tid == 0 && s_roots <= 1) g_done[mat] = 1;
}

// ---------------- bitonic sort (warp-local low phases) + fused final loss ----------------
__global__ void __launch_bounds__(1024) sort_kernel(float* __restrict__ out) {
    int mat = blockIdx.x;
    __shared__ float s[NPTS];
    __shared__ float red[1024];
    __shared__ int s_last;
    int tid = threadIdx.x;

    for (int i = tid; i < NPTS; i += 1024)
        s[i] = g_deaths[mat][i];             // 4095 deaths + one 0 (surviving root's slot)
    __syncthreads();
    for (int k = 2; k <= NPTS; k <<= 1)
        for (int j2 = k >> 1; j2 > 0; j2 >>= 1) {
            for (int i = tid; i < NPTS; i += 1024) {
                int ixj = i ^ j2;
                if (ixj > i) {
                    float a = s[i], b = s[ixj];
                    bool up = ((i & k) == 0);
                    if ((a > b) == up) { s[i] = b; s[ixj] = a; }
                }
            }
            int next = (j2 > 1) ? (j2 >> 1) : k;   // k-boundary: next distance is k
            if (next >= 32) __syncthreads();
            else            __syncwarp(0xffffffffu);
        }
    __syncthreads();
    for (int i = tid; i < NPTS; i += 1024)
        g_deaths[mat][i] = s[i];

    // ---- last sorted block computes the final loss ----
    __threadfence();
    __syncthreads();
    if (tid == 0) s_last = (atomicAdd(&g_sortcnt, 1) == 1);
    __syncthreads();
    if (!s_last) return;
    __threadfence();
    const float inv = 1.0f / ((float)NPTS * (float)DIM);
    float acc = 0.f;
    for (int i = tid; i < NPTS; i += 1024) {
        float a = g_deaths[0][i], b = g_deaths[1][i];
        acc += fminf(fabsf(a - b), 0.5f * (a + b));
        acc += g_rowdiff[i] * inv;
    }
    red[tid] = acc; __syncthreads();
    #pragma unroll
    for (int st = 512; st > 0; st >>= 1) {
        if (tid < st) red[tid] += red[tid + st];
        __syncthreads();
    }
    if (tid == 0) out[0] = red[0];
}

extern "C" void kernel_launch(void* const* d_in, const int* in_sizes, int n_in,
                              void* d_out, int out_size) {
    const float* x1 = (const float*)d_in[0];
    const float* x2 = (const float*)d_in[1];
    float* out = (float*)d_out;

    cudaFuncSetAttribute(dist_hmma_kernel, cudaFuncAttributeMaxDynamicSharedMemorySize, 65536);

    prep_kernel<<<1024, 256>>>(x1, x2);
    dist_hmma_kernel<<<dim3(528, 1, 2), 256, 65536>>>();
    for (int r = 0; r < 12; r++) {
        boruvka_scan <<<1024, 256>>>();
        boruvka_merge<<<2, 1024>>>();
    }
    sort_kernel<<<2, 1024>>>(out);
}

// round 15
// speedup vs baseline: 1.0545x; 1.0104x over previous
#include <cuda_runtime.h>
#include <cuda_bf16.h>
#include <math.h>
#include <stdint.h>

#define NPTS 4096
#define DIM  512
#define KPK  1024              // packed storage: [hi | lo]
#define NSTAGE 24              // GEMM K = 1536 via chunk maps into the 1024 storage
#define BK   64
#define BIGF   1e30f
#define INFKEY 0xFFFFFFFFFFFFFFFFull
#define TRANS_LD 132

// ---------------- scratch (static device globals; no allocation) ----------------
__device__ float g_dist[2][(size_t)NPTS * NPTS];            // 2 x 64MB distance matrices
__device__ __nv_bfloat16 g_pk[2][(size_t)NPTS * KPK];       // [hi | lo] packed operands
__device__ float g_sq[2][NPTS];                             // squared norms (fp32)
__device__ float g_rowdiff[NPTS];                           // per-row (x1-x2)^2 sums
__device__ float g_deaths[2][NPTS];                         // slot-based deaths (root id = slot)
__device__ int   g_comp[2][NPTS];                           // Boruvka component labels
__device__ unsigned long long g_lanebest[2][NPTS][32];      // per-lane cached min outgoing
__device__ unsigned long long g_rowbest[2][NPTS];           // per-row best outgoing edge key
__device__ int   g_done[2];
__device__ int   g_sortcnt;                                 // sort-block arrival counter

// ---------------- helpers ----------------
__device__ __forceinline__ uint32_t smem_u32(const void* p) {
    uint32_t a;
    asm("{ .reg .u64 t; cvta.to.shared.u64 t, %1; cvt.u32.u64 %0, t; }" : "=r"(a) : "l"(p));
    return a;
}
__device__ __forceinline__ uint32_t swz(uint32_t b) { return b ^ ((b >> 3) & 0x70); }

__device__ __forceinline__ void cp16(uint32_t s, const void* g) {
    asm volatile("cp.async.cg.shared.global [%0], [%1], 16;" :: "r"(s), "l"(g));
}
__device__ __forceinline__ void ldsm4(uint32_t& r0, uint32_t& r1, uint32_t& r2, uint32_t& r3,
                                      uint32_t a) {
    asm volatile("ldmatrix.sync.aligned.m8n8.x4.shared.b16 {%0,%1,%2,%3}, [%4];"
                 : "=r"(r0), "=r"(r1), "=r"(r2), "=r"(r3) : "r"(a));
}
__device__ __forceinline__ void mma16816(float* c, const uint32_t* a, const uint32_t* b) {
    asm volatile("mma.sync.aligned.m16n8k16.row.col.f32.bf16.bf16.f32 "
                 "{%0,%1,%2,%3}, {%4,%5,%6,%7}, {%8,%9}, {%0,%1,%2,%3};"
                 : "+f"(c[0]), "+f"(c[1]), "+f"(c[2]), "+f"(c[3])
                 : "r"(a[0]), "r"(a[1]), "r"(a[2]), "r"(a[3]), "r"(b[0]), "r"(b[1]));
}

// ---------------- prep: hi/lo packed + sq norms + L2-diff + ALL init (warp/row) ----------------
__global__ void prep_kernel(const float* __restrict__ x1, const float* __restrict__ x2) {
    int w    = (blockIdx.x * 256 + threadIdx.x) >> 5;   // 0..8191
    int lane = threadIdx.x & 31;
    int mat  = w >> 12;
    int row  = w & (NPTS - 1);
    const float* p = (mat ? x2 : x1) + (size_t)row * DIM;
    const float* q = x2 + (size_t)row * DIM;
    __nv_bfloat16* pa = g_pk[mat] + (size_t)row * KPK;
    float s = 0.f, sd = 0.f;
    for (int c = lane * 4; c < DIM; c += 128) {
        float4 v = *(const float4*)(p + c);
        __nv_bfloat16 h0 = __float2bfloat16(v.x), h1 = __float2bfloat16(v.y);
        __nv_bfloat16 h2 = __float2bfloat16(v.z), h3 = __float2bfloat16(v.w);
        __nv_bfloat16 l0 = __float2bfloat16(v.x - __bfloat162float(h0));
        __nv_bfloat16 l1 = __float2bfloat16(v.y - __bfloat162float(h1));
        __nv_bfloat16 l2 = __float2bfloat16(v.z - __bfloat162float(h2));
        __nv_bfloat16 l3 = __float2bfloat16(v.w - __bfloat162float(h3));
        ushort4 hs = make_ushort4(__bfloat16_as_ushort(h0), __bfloat16_as_ushort(h1),
                                  __bfloat16_as_ushort(h2), __bfloat16_as_ushort(h3));
        ushort4 ls = make_ushort4(__bfloat16_as_ushort(l0), __bfloat16_as_ushort(l1),
                                  __bfloat16_as_ushort(l2), __bfloat16_as_ushort(l3));
        *(ushort4*)(pa + c)       = hs;    // chunks 0-7:  hi
        *(ushort4*)(pa + 512 + c) = ls;    // chunks 8-15: lo
        s += v.x * v.x + v.y * v.y + v.z * v.z + v.w * v.w;
        if (mat == 0) {
            float4 u = *(const float4*)(q + c);
            float d0 = v.x - u.x, d1 = v.y - u.y, d2 = v.z - u.z, d3 = v.w - u.w;
            sd += d0 * d0 + d1 * d1 + d2 * d2 + d3 * d3;
        }
    }
    #pragma unroll
    for (int o = 16; o > 0; o >>= 1) {
        s  += __shfl_xor_sync(0xffffffffu, s, o);
        sd += __shfl_xor_sync(0xffffffffu, sd, o);
    }
    // fused init
    g_lanebest[mat][row][lane] = 0ull;   // 0 = "must scan" sentinel
    if (lane == 0) {
        g_sq[mat][row] = s;
        if (mat == 0) g_rowdiff[row] = sd;
        g_comp[mat][row] = row;
        g_rowbest[mat][row] = INFKEY;
        g_deaths[mat][row] = 0.0f;       // slot-based recording; root slot stays 0
    }
    if (w == 0) {
        if (lane < 2) g_done[lane] = 0;
        if (lane == 0) g_sortcnt = 0;
    }
}

// ---------------- distance matrix: mma.sync bf16 GEMM, M128 N128, K=1536 via chunk maps ----------
// 8 warps (4m x 2n), warp tile 32x64, BK=64 (128B rows, conflict-free ldmatrix), 2-stage.
// Effective A = [hi|lo|hi], B = [hi|hi|lo], both read from the single [hi|lo] packed array.
__global__ void __launch_bounds__(256, 2) dist_hmma_kernel() {
    extern __shared__ __align__(128) unsigned char sraw[];
    int mat = blockIdx.z;
    int t = blockIdx.x, bi = 0, len = 32;
    while (t >= len) { t -= len; len--; bi++; }
    int bj = bi + t;

    const __nv_bfloat16* pk = g_pk[mat];
    float* Dst = g_dist[mat];
    int tid = threadIdx.x, lane = tid & 31, wid = tid >> 5;
    int wm = wid & 3, wn = wid >> 2;           // warp tile: rows wm*32, cols wn*64
    uint32_t sb = smem_u32(sraw);

    float acc[2][8][4];
    #pragma unroll
    for (int im = 0; im < 2; im++)
        #pragma unroll
        for (int in = 0; in < 8; in++)
            #pragma unroll
            for (int q = 0; q < 4; q++) acc[im][in][q] = 0.f;

    int rowA0 = bi * 128, rowB0 = bj * 128;
    // per-stage chunk maps into the [hi|lo] storage (in elements):
    //   A stage s: s<16 -> s ; s>=16 -> s-16   (hi,lo,hi)
    //   B stage s: s<8  -> s ; s>=8  -> s-8    (hi,hi,lo)
    #define ISSUE(s) do {                                                           \
        int _b = (s) & 1;                                                           \
        int _ka = (((s) < 16) ? (s) : (s) - 16) * BK;                               \
        int _kb = (((s) <  8) ? (s) : (s) -  8) * BK;                               \
        _Pragma("unroll")                                                           \
        for (int _h = 0; _h < 4; _h++) {                                            \
            int _tt = tid + _h * 256;                                               \
            int _row = _tt >> 3, _c16 = _tt & 7;                                    \
            uint32_t _so = swz((uint32_t)(_row * 128 + _c16 * 16));                 \
            cp16(sb + _b * 16384 + _so,                                             \
                 pk + (size_t)(rowA0 + _row) * KPK + _ka + _c16 * 8);               \
            cp16(sb + 32768 + _b * 16384 + _so,                                     \
                 pk + (size_t)(rowB0 + _row) * KPK + _kb + _c16 * 8);               \
        }                                                                           \
        asm volatile("cp.async.commit_group;" ::: "memory");                        \
    } while (0)

    ISSUE(0);
    for (int s = 0; s < NSTAGE; s++) {
        if (s < NSTAGE - 1) { ISSUE(s + 1); asm volatile("cp.async.wait_group 1;" ::: "memory"); }
        else                {               asm volatile("cp.async.wait_group 0;" ::: "memory"); }
        __syncthreads();
        uint32_t baseA = sb + (s & 1) * 16384;
        uint32_t baseB = sb + 32768 + (s & 1) * 16384;
        #pragma unroll
        for (int kk = 0; kk < 4; kk++) {
            uint32_t a[2][4], bb[8][2];
            #pragma unroll
            for (int im = 0; im < 2; im++) {
                uint32_t addr = baseA + swz((uint32_t)((wm * 32 + im * 16 + (lane & 15)) * 128
                                                       + kk * 32 + (lane >> 4) * 16));
                ldsm4(a[im][0], a[im][1], a[im][2], a[im][3], addr);
            }
            #pragma unroll
            for (int np = 0; np < 4; np++) {
                uint32_t addr = baseB + swz((uint32_t)((wn * 64 + np * 16 + ((lane >> 4) << 3)
                                                        + (lane & 7)) * 128
                                                       + kk * 32 + ((lane >> 3) & 1) * 16));
                uint32_t r0, r1, r2, r3;
                ldsm4(r0, r1, r2, r3, addr);
                bb[np * 2][0] = r0; bb[np * 2][1] = r1;
                bb[np * 2 + 1][0] = r2; bb[np * 2 + 1][1] = r3;
            }
            #pragma unroll
            for (int im = 0; im < 2; im++)
                #pragma unroll
                for (int in = 0; in < 8; in++)
                    mma16816(acc[im][in], a[im], bb[in]);
        }
        __syncthreads();
    }
    #undef ISSUE

    // ---- epilogue: dist transform + row-major stores ----
    bool diag = (bi == bj);
    int giBase = bi * 128, gjBase = bj * 128;
    float sqr[2][2], sqc[8][2];
    #pragma unroll
    for (int im = 0; im < 2; im++)
        #pragma unroll
        for (int p = 0; p < 2; p++)
            sqr[im][p] = g_sq[mat][giBase + wm * 32 + im * 16 + (lane >> 2) + p * 8];
    #pragma unroll
    for (int in = 0; in < 8; in++) {
        int col = gjBase + wn * 64 + in * 8 + (lane & 3) * 2;
        sqc[in][0] = g_sq[mat][col];
        sqc[in][1] = g_sq[mat][col + 1];
    }
    #pragma unroll
    for (int im = 0; im < 2; im++) {
        #pragma unroll
        for (int in = 0; in < 8; in++) {
            #pragma unroll
            for (int p = 0; p < 2; p++) {
                int m = giBase + wm * 32 + im * 16 + (lane >> 2) + p * 8;
                int n = gjBase + wn * 64 + in * 8 + (lane & 3) * 2;
                float d0 = sqr[im][p] + sqc[in][0] - 2.f * acc[im][in][p * 2];
                float d1 = sqr[im][p] + sqc[in][1] - 2.f * acc[im][in][p * 2 + 1];
                d0 = sqrtf(fmaxf(d0, 1e-12f));
                d1 = sqrtf(fmaxf(d1, 1e-12f));
                if (diag) { if (m == n) d0 = BIGF; if (m == n + 1) d1 = BIGF; }
                acc[im][in][p * 2]     = d0;
                acc[im][in][p * 2 + 1] = d1;
                *(float2*)(Dst + (size_t)m * NPTS + n) = make_float2(d0, d1);
            }
        }
    }

    // ---- mirror via smem transpose (two 64-col chunks; 64 rows x 4 segs of 32) ----
    if (!diag) {
        float* trans = (float*)sraw;
        #pragma unroll
        for (int h = 0; h < 2; h++) {
            __syncthreads();
            if (wn == h) {
                #pragma unroll
                for (int im = 0; im < 2; im++)
                    #pragma unroll
                    for (int in = 0; in < 8; in++)
                        #pragma unroll
                        for (int p = 0; p < 2; p++) {
                            int ml = wm * 32 + im * 16 + (lane >> 2) + p * 8;
                            int nl = in * 8 + (lane & 3) * 2;
                            trans[nl * TRANS_LD + ml]       = acc[im][in][p * 2];
                            trans[(nl + 1) * TRANS_LD + ml] = acc[im][in][p * 2 + 1];
                        }
            }
            __syncthreads();
            int r = tid >> 2, seg = tid & 3;
            const float* srcp = trans + r * TRANS_LD + seg * 32;
            float* dstp = Dst + (size_t)(gjBase + h * 64 + r) * NPTS + giBase + seg * 32;
            #pragma unroll
            for (int i = 0; i < 8; i++)
                *(float4*)(dstp + i * 4) = *(const float4*)(srcp + i * 4);
        }
    }
}

// ---------------- Boruvka scan: warp/row, per-lane exact cache ----------------
__global__ void __launch_bounds__(256) boruvka_scan() {
    int w    = (blockIdx.x * 256 + threadIdx.x) >> 5;   // 0..8191
    int lane = threadIdx.x & 31;
    int mat  = w >> 12;
    int row  = w & (NPTS - 1);
    if (g_done[mat]) return;

    int myc = g_comp[mat][row];
    unsigned long long lk = g_lanebest[mat][row][lane];

    bool need = (lk == 0ull);
    if (!need && lk != INFKEY) {
        int eid = (int)(lk & 0xFFFFFF);
        int u = eid >> 12, v = eid & (NPTS - 1);
        int other = (u == row) ? v : u;
        need = (g_comp[mat][other] == myc);
    }
    if (need) {
        const float4* drow = (const float4*)(g_dist[mat] + (size_t)row * NPTS);
        const int4*   crow = (const int4*)(g_comp[mat]);
        int rowsh = row << 12;
        unsigned long long best = INFKEY;
        #pragma unroll 4
        for (int t = lane; t < NPTS / 4; t += 32) {
            float4 d = drow[t];
            int4   c = crow[t];
            int k = t * 4;
            if (c.x != myc) {
                int id = (k < row) ? ((k << 12) | row) : (rowsh | k);
                best = min(best, ((unsigned long long)__float_as_uint(d.x) << 24)
                                 | (unsigned long long)id);
            }
            if (c.y != myc) {
                int k1 = k + 1;
                int id = (k1 < row) ? ((k1 << 12) | row) : (rowsh | k1);
                best = min(best, ((unsigned long long)__float_as_uint(d.y) << 24)
                                 | (unsigned long long)id);
            }
            if (c.z != myc) {
                int k2 = k + 2;
                int id = (k2 < row) ? ((k2 << 12) | row) : (rowsh | k2);
                best = min(best, ((unsigned long long)__float_as_uint(d.z) << 24)
                                 | (unsigned long long)id);
            }
            if (c.w != myc) {
                int k3 = k + 3;
                int id = (k3 < row) ? ((k3 << 12) | row) : (rowsh | k3);
                best = min(best, ((unsigned long long)__float_as_uint(d.w) << 24)
                                 | (unsigned long long)id);
            }
        }
        lk = best;
        g_lanebest[mat][row][lane] = lk;
    }
    __syncwarp(0xffffffffu);
    unsigned long long rb = lk;
    #pragma unroll
    for (int o = 16; o > 0; o >>= 1) {
        unsigned long long other = __shfl_xor_sync(0xffffffffu, rb, o);
        rb = min(rb, other);
    }
    if (lane == 0) g_rowbest[mat][row] = rb;
}

// ---------------- Boruvka merge: prefetched, fused cycle-break, slot deaths ----------------
__global__ void __launch_bounds__(1024) boruvka_merge() {
    int mat = blockIdx.x;
    if (g_done[mat]) return;

    __shared__ unsigned long long sbest[NPTS];   // 32KB
    __shared__ unsigned short    par[NPTS];      // 8KB
    __shared__ int s_roots;

    int tid = threadIdx.x;

    // prefetch rowbest + comp (overlaps DRAM latency with sbest init)
    unsigned long long kreg[4];
    int creg[4];
    #pragma unroll
    for (int j = 0; j < 4; j++) {
        int r = tid + j * 1024;
        kreg[j] = g_rowbest[mat][r];
        creg[j] = g_comp[mat][r];
    }
    #pragma unroll
    for (int j = 0; j < 4; j++) sbest[tid + j * 1024] = INFKEY;
    __syncthreads();

    #pragma unroll
    for (int j = 0; j < 4; j++)
        if (kreg[j] != INFKEY) atomicMin(&sbest[creg[j]], kreg[j]);
    __syncthreads();

    // hook + inline mutual-cycle break + slot-based death record
    #pragma unroll
    for (int j = 0; j < 4; j++) {
        int c = tid + j * 1024;
        unsigned long long k = sbest[c];
        int p = c;
        if (k != INFKEY) {
            int eid = (int)(k & 0xFFFFFF);
            int u = eid >> 12, v = eid & (NPTS - 1);
            int cu = g_comp[mat][u];
            int d = (cu == c) ? g_comp[mat][v] : cu;
            bool survivor = (sbest[d] == k) && (c < d);   // mutual pair, smaller root wins
            p = survivor ? c : d;
            if (!survivor)
                g_deaths[mat][c] = __uint_as_float((unsigned)(k >> 24));
        }
        par[c] = (unsigned short)p;
    }
    __syncthreads();

    // pointer jumping with convergence early-exit
    for (int it = 0; it < 12; it++) {
        int changed = 0;
        #pragma unroll
        for (int j = 0; j < 4; j++) {
            int c = tid + j * 1024;
            int p = par[c];
            int gp = par[p];
            if (gp != p) { par[c] = (unsigned short)gp; changed = 1; }
        }
        if (!__syncthreads_or(changed)) break;
    }

    if (tid == 0) s_roots = 0;
    __syncthreads();
    int rootcnt = 0;
    #pragma unroll
    for (int j = 0; j < 4; j++) {
        int i = tid + j * 1024;
        int nc = par[creg[j]];
        g_comp[mat][i] = nc;
        rootcnt += (nc == i);
    }
    #pragma unroll
    for (int o = 16; o > 0; o >>= 1) rootcnt += __shfl_xor_sync(0xffffffffu, rootcnt, o);
    if ((tid & 31) == 0 && rootcnt) atomicAdd(&s_roots, rootcnt);
    __syncthreads();
    if (tid == 0 && s_roots <= 1) g_done[mat] = 1;
}

// ---------------- bitonic sort (warp-local low phases) + fused final loss ----------------
__global__ void __launch_bounds__(1024) sort_kernel(float* __restrict__ out) {
    int mat = blockIdx.x;
    __shared__ float s[NPTS];
    __shared__ float red[1024];
    __shared__ int s_last;
    int tid = threadIdx.x;

    for (int i = tid; i < NPTS; i += 1024)
        s[i] = g_deaths[mat][i];             // 4095 deaths + one 0 (surviving root's slot)
    __syncthreads();
    for (int k = 2; k <= NPTS; k <<= 1)
        for (int j2 = k >> 1; j2 > 0; j2 >>= 1) {
            for (int i = tid; i < NPTS; i += 1024) {
                int ixj = i ^ j2;
                if (ixj > i) {
                    float a = s[i], b = s[ixj];
                    bool up = ((i & k) == 0);
                    if ((a > b) == up) { s[i] = b; s[ixj] = a; }
                }
            }
            int next = (j2 > 1) ? (j2 >> 1) : k;   // k-boundary: next distance is k
            if (next >= 32) __syncthreads();
            else            __syncwarp(0xffffffffu);
        }
    __syncthreads();
    for (int i = tid; i < NPTS; i += 1024)
        g_deaths[mat][i] = s[i];

    // ---- last sorted block computes the final loss ----
    __threadfence();
    __syncthreads();
    if (tid == 0) s_last = (atomicAdd(&g_sortcnt, 1) == 1);
    __syncthreads();
    if (!s_last) return;
    __threadfence();
    const float inv = 1.0f / ((float)NPTS * (float)DIM);
    float acc = 0.f;
    for (int i = tid; i < NPTS; i += 1024) {
        float a = g_deaths[0][i], b = g_deaths[1][i];
        acc += fminf(fabsf(a - b), 0.5f * (a + b));
        acc += g_rowdiff[i] * inv;
    }
    red[tid] = acc; __syncthreads();
    #pragma unroll
    for (int st = 512; st > 0; st >>= 1) {
        if (tid < st) red[tid] += red[tid + st];
        __syncthreads();
    }
    if (tid == 0) out[0] = red[0];
}

extern "C" void kernel_launch(void* const* d_in, const int* in_sizes, int n_in,
                              void* d_out, int out_size) {
    const float* x1 = (const float*)d_in[0];
    const float* x2 = (const float*)d_in[1];
    float* out = (float*)d_out;

    cudaFuncSetAttribute(dist_hmma_kernel, cudaFuncAttributeMaxDynamicSharedMemorySize, 65536);

    prep_kernel<<<1024, 256>>>(x1, x2);
    dist_hmma_kernel<<<dim3(528, 1, 2), 256, 65536>>>();
    for (int r = 0; r < 12; r++) {
        boruvka_scan <<<1024, 256>>>();
        boruvka_merge<<<2, 1024>>>();
    }
    sort_kernel<<<2, 1024>>>(out);
}

// round 17
// speedup vs baseline: 1.0686x; 1.0133x over previous
#include <cuda_runtime.h>
#include <cuda_bf16.h>
#include <math.h>
#include <stdint.h>

#define NPTS 4096
#define DIM  512
#define KPK  1024              // packed storage: [hi | lo] (bf16)
#define NSTAGE 24              // GEMM K = 1536 via chunk maps into the 1024 storage
#define BK   64
#define BIGF   1e30f
#define INFKEY 0xFFFFFFFFFFFFFFFFull
#define TRANS_LD 132

// ---------------- scratch (static device globals; no allocation) ----------------
__device__ float g_dist[2][(size_t)NPTS * NPTS];            // 2 x 64MB SQUARED-distance matrices
__device__ __nv_bfloat16 g_pk[2][(size_t)NPTS * KPK];       // [hi | lo] packed operands
__device__ float g_sq[2][NPTS];                             // squared norms (fp32)
__device__ float g_rowdiff[NPTS];                           // per-row (x1-x2)^2 sums
__device__ float g_deaths[2][NPTS];                         // slot-based deaths (d^2; root id = slot)
__device__ int   g_comp[2][NPTS];                           // Boruvka component labels
__device__ unsigned long long g_lanebest[2][NPTS][32];      // per-lane cached min outgoing
__device__ unsigned long long g_rowbest[2][NPTS];           // per-row best outgoing edge key
__device__ int   g_done[2];
__device__ int   g_sortcnt;                                 // sort-block arrival counter

// ---------------- helpers ----------------
__device__ __forceinline__ uint32_t smem_u32(const void* p) {
    uint32_t a;
    asm("{ .reg .u64 t; cvta.to.shared.u64 t, %1; cvt.u32.u64 %0, t; }" : "=r"(a) : "l"(p));
    return a;
}
__device__ __forceinline__ uint32_t swz(uint32_t b) { return b ^ ((b >> 3) & 0x70); }

__device__ __forceinline__ void cp16(uint32_t s, const void* g) {
    asm volatile("cp.async.cg.shared.global [%0], [%1], 16;" :: "r"(s), "l"(g));
}
__device__ __forceinline__ void ldsm4(uint32_t& r0, uint32_t& r1, uint32_t& r2, uint32_t& r3,
                                      uint32_t a) {
    asm volatile("ldmatrix.sync.aligned.m8n8.x4.shared.b16 {%0,%1,%2,%3}, [%4];"
                 : "=r"(r0), "=r"(r1), "=r"(r2), "=r"(r3) : "r"(a));
}
__device__ __forceinline__ void mma16816(float* c, const uint32_t* a, const uint32_t* b) {
    asm volatile("mma.sync.aligned.m16n8k16.row.col.f32.bf16.bf16.f32 "
                 "{%0,%1,%2,%3}, {%4,%5,%6,%7}, {%8,%9}, {%0,%1,%2,%3};"
                 : "+f"(c[0]), "+f"(c[1]), "+f"(c[2]), "+f"(c[3])
                 : "r"(a[0]), "r"(a[1]), "r"(a[2]), "r"(a[3]), "r"(b[0]), "r"(b[1]));
}

// ---------------- prep: hi/lo packed + sq norms + L2-diff + ALL init (warp/row) ----------------
__global__ void prep_kernel(const float* __restrict__ x1, const float* __restrict__ x2) {
    int w    = (blockIdx.x * 256 + threadIdx.x) >> 5;   // 0..8191
    int lane = threadIdx.x & 31;
    int mat  = w >> 12;
    int row  = w & (NPTS - 1);
    const float* p = (mat ? x2 : x1) + (size_t)row * DIM;
    const float* q = x2 + (size_t)row * DIM;
    __nv_bfloat16* pa = g_pk[mat] + (size_t)row * KPK;
    float s = 0.f, sd = 0.f;
    for (int c = lane * 4; c < DIM; c += 128) {
        float4 v = *(const float4*)(p + c);
        __nv_bfloat16 h0 = __float2bfloat16(v.x), h1 = __float2bfloat16(v.y);
        __nv_bfloat16 h2 = __float2bfloat16(v.z), h3 = __float2bfloat16(v.w);
        __nv_bfloat16 l0 = __float2bfloat16(v.x - __bfloat162float(h0));
        __nv_bfloat16 l1 = __float2bfloat16(v.y - __bfloat162float(h1));
        __nv_bfloat16 l2 = __float2bfloat16(v.z - __bfloat162float(h2));
        __nv_bfloat16 l3 = __float2bfloat16(v.w - __bfloat162float(h3));
        ushort4 hs = make_ushort4(__bfloat16_as_ushort(h0), __bfloat16_as_ushort(h1),
                                  __bfloat16_as_ushort(h2), __bfloat16_as_ushort(h3));
        ushort4 ls = make_ushort4(__bfloat16_as_ushort(l0), __bfloat16_as_ushort(l1),
                                  __bfloat16_as_ushort(l2), __bfloat16_as_ushort(l3));
        *(ushort4*)(pa + c)       = hs;    // chunks 0-7:  hi
        *(ushort4*)(pa + 512 + c) = ls;    // chunks 8-15: lo
        s += v.x * v.x + v.y * v.y + v.z * v.z + v.w * v.w;
        if (mat == 0) {
            float4 u = *(const float4*)(q + c);
            float d0 = v.x - u.x, d1 = v.y - u.y, d2 = v.z - u.z, d3 = v.w - u.w;
            sd += d0 * d0 + d1 * d1 + d2 * d2 + d3 * d3;
        }
    }
    #pragma unroll
    for (int o = 16; o > 0; o >>= 1) {
        s  += __shfl_xor_sync(0xffffffffu, s, o);
        sd += __shfl_xor_sync(0xffffffffu, sd, o);
    }
    // fused init
    g_lanebest[mat][row][lane] = 0ull;   // 0 = "must scan" sentinel
    if (lane == 0) {
        g_sq[mat][row] = s;
        if (mat == 0) g_rowdiff[row] = sd;
        g_comp[mat][row] = row;
        g_rowbest[mat][row] = INFKEY;
        g_deaths[mat][row] = 0.0f;       // slot-based recording; root slot stays 0
    }
    if (w == 0) {
        if (lane < 2) g_done[lane] = 0;
        if (lane == 0) g_sortcnt = 0;
    }
}

// ---------------- squared-distance matrix: mma.sync bf16 GEMM, M128 N128, K=1536 ----------------
// 8 warps (4m x 2n), warp tile 32x64, BK=64 (128B rows, conflict-free ldmatrix), 2-stage.
// Effective A = [hi|lo|hi], B = [hi|hi|lo] via chunk maps on the [hi|lo] packed array.
// Epilogue stores d^2 (sqrt deferred to sort; monotone bit-order => identical MST).
__global__ void __launch_bounds__(256, 2) dist_hmma_kernel() {
    extern __shared__ __align__(128) unsigned char sraw[];
    int mat = blockIdx.z;
    int t = blockIdx.x, bi = 0, len = 32;
    while (t >= len) { t -= len; len--; bi++; }
    int bj = bi + t;

    const __nv_bfloat16* pk = g_pk[mat];
    float* Dst = g_dist[mat];
    int tid = threadIdx.x, lane = tid & 31, wid = tid >> 5;
    int wm = wid & 3, wn = wid >> 2;           // warp tile: rows wm*32, cols wn*64
    uint32_t sb = smem_u32(sraw);

    float acc[2][8][4];
    #pragma unroll
    for (int im = 0; im < 2; im++)
        #pragma unroll
        for (int in = 0; in < 8; in++)
            #pragma unroll
            for (int q = 0; q < 4; q++) acc[im][in][q] = 0.f;

    int rowA0 = bi * 128, rowB0 = bj * 128;
    // per-stage chunk maps into [hi|lo] storage (elements):
    //   A stage s: s<16 -> s ; s>=16 -> s-16   (hi,lo,hi)
    //   B stage s: s<8  -> s ; s>=8  -> s-8    (hi,hi,lo)
    #define ISSUE(s) do {                                                           \
        int _b = (s) & 1;                                                           \
        int _ka = (((s) < 16) ? (s) : (s) - 16) * BK;                               \
        int _kb = (((s) <  8) ? (s) : (s) -  8) * BK;                               \
        _Pragma("unroll")                                                           \
        for (int _h = 0; _h < 4; _h++) {                                            \
            int _tt = tid + _h * 256;                                               \
            int _row = _tt >> 3, _c16 = _tt & 7;                                    \
            uint32_t _so = swz((uint32_t)(_row * 128 + _c16 * 16));                 \
            cp16(sb + _b * 16384 + _so,                                             \
                 pk + (size_t)(rowA0 + _row) * KPK + _ka + _c16 * 8);               \
            cp16(sb + 32768 + _b * 16384 + _so,                                     \
                 pk + (size_t)(rowB0 + _row) * KPK + _kb + _c16 * 8);               \
        }                                                                           \
        asm volatile("cp.async.commit_group;" ::: "memory");                        \
    } while (0)

    ISSUE(0);
    for (int s = 0; s < NSTAGE; s++) {
        if (s < NSTAGE - 1) { ISSUE(s + 1); asm volatile("cp.async.wait_group 1;" ::: "memory"); }
        else                {               asm volatile("cp.async.wait_group 0;" ::: "memory"); }
        __syncthreads();
        uint32_t baseA = sb + (s & 1) * 16384;
        uint32_t baseB = sb + 32768 + (s & 1) * 16384;
        #pragma unroll
        for (int kk = 0; kk < 4; kk++) {
            uint32_t a[2][4], bb[8][2];
            #pragma unroll
            for (int im = 0; im < 2; im++) {
                uint32_t addr = baseA + swz((uint32_t)((wm * 32 + im * 16 + (lane & 15)) * 128
                                                       + kk * 32 + (lane >> 4) * 16));
                ldsm4(a[im][0], a[im][1], a[im][2], a[im][3], addr);
            }
            #pragma unroll
            for (int np = 0; np < 4; np++) {
                uint32_t addr = baseB + swz((uint32_t)((wn * 64 + np * 16 + ((lane >> 4) << 3)
                                                        + (lane & 7)) * 128
                                                       + kk * 32 + ((lane >> 3) & 1) * 16));
                uint32_t r0, r1, r2, r3;
                ldsm4(r0, r1, r2, r3, addr);
                bb[np * 2][0] = r0; bb[np * 2][1] = r1;
                bb[np * 2 + 1][0] = r2; bb[np * 2 + 1][1] = r3;
            }
            #pragma unroll
            for (int im = 0; im < 2; im++)
                #pragma unroll
                for (int in = 0; in < 8; in++)
                    mma16816(acc[im][in], a[im], bb[in]);
        }
        __syncthreads();
    }
    #undef ISSUE

    // ---- epilogue: d^2 transform (no sqrt) + row-major stores ----
    bool diag = (bi == bj);
    int giBase = bi * 128, gjBase = bj * 128;
    float sqr[2][2], sqc[8][2];
    #pragma unroll
    for (int im = 0; im < 2; im++)
        #pragma unroll
        for (int p = 0; p < 2; p++)
            sqr[im][p] = g_sq[mat][giBase + wm * 32 + im * 16 + (lane >> 2) + p * 8];
    #pragma unroll
    for (int in = 0; in < 8; in++) {
        int col = gjBase + wn * 64 + in * 8 + (lane & 3) * 2;
        sqc[in][0] = g_sq[mat][col];
        sqc[in][1] = g_sq[mat][col + 1];
    }
    #pragma unroll
    for (int im = 0; im < 2; im++) {
        #pragma unroll
        for (int in = 0; in < 8; in++) {
            #pragma unroll
            for (int p = 0; p < 2; p++) {
                int m = giBase + wm * 32 + im * 16 + (lane >> 2) + p * 8;
                int n = gjBase + wn * 64 + in * 8 + (lane & 3) * 2;
                float d0 = sqr[im][p] + sqc[in][0] - 2.f * acc[im][in][p * 2];
                float d1 = sqr[im][p] + sqc[in][1] - 2.f * acc[im][in][p * 2 + 1];
                if (diag) { if (m == n) d0 = BIGF; if (m == n + 1) d1 = BIGF; }
                acc[im][in][p * 2]     = d0;
                acc[im][in][p * 2 + 1] = d1;
                *(float2*)(Dst + (size_t)m * NPTS + n) = make_float2(d0, d1);
            }
        }
    }

    // ---- mirror via smem transpose (two 64-col chunks; 64 rows x 4 segs of 32) ----
    if (!diag) {
        float* trans = (float*)sraw;
        #pragma unroll
        for (int h = 0; h < 2; h++) {
            __syncthreads();
            if (wn == h) {
                #pragma unroll
                for (int im = 0; im < 2; im++)
                    #pragma unroll
                    for (int in = 0; in < 8; in++)
                        #pragma unroll
                        for (int p = 0; p < 2; p++) {
                            int ml = wm * 32 + im * 16 + (lane >> 2) + p * 8;
                            int nl = in * 8 + (lane & 3) * 2;
                            trans[nl * TRANS_LD + ml]       = acc[im][in][p * 2];
                            trans[(nl + 1) * TRANS_LD + ml] = acc[im][in][p * 2 + 1];
                        }
            }
            __syncthreads();
            int r = tid >> 2, seg = tid & 3;
            const float* srcp = trans + r * TRANS_LD + seg * 32;
            float* dstp = Dst + (size_t)(gjBase + h * 64 + r) * NPTS + giBase + seg * 32;
            #pragma unroll
            for (int i = 0; i < 8; i++)
                *(float4*)(dstp + i * 4) = *(const float4*)(srcp + i * 4);
        }
    }
}

// ---------------- Boruvka scan: warp/row, per-lane exact cache (keys on d^2 bits) ----------------
__global__ void __launch_bounds__(256) boruvka_scan() {
    int w    = (blockIdx.x * 256 + threadIdx.x) >> 5;   // 0..8191
    int lane = threadIdx.x & 31;
    int mat  = w >> 12;
    int row  = w & (NPTS - 1);
    if (g_done[mat]) return;

    int myc = g_comp[mat][row];
    unsigned long long lk = g_lanebest[mat][row][lane];

    bool need = (lk == 0ull);
    if (!need && lk != INFKEY) {
        int eid = (int)(lk & 0xFFFFFF);
        int u = eid >> 12, v = eid & (NPTS - 1);
        int other = (u == row) ? v : u;
        need = (g_comp[mat][other] == myc);
    }
    if (need) {
        const float4* drow = (const float4*)(g_dist[mat] + (size_t)row * NPTS);
        const int4*   crow = (const int4*)(g_comp[mat]);
        int rowsh = row << 12;
        unsigned long long best = INFKEY;
        #pragma unroll 4
        for (int t = lane; t < NPTS / 4; t += 32) {
            float4 d = drow[t];
            int4   c = crow[t];
            int k = t * 4;
            if (c.x != myc) {
                int id = (k < row) ? ((k << 12) | row) : (rowsh | k);
                best = min(best, ((unsigned long long)__float_as_uint(d.x) << 24)
                                 | (unsigned long long)id);
            }
            if (c.y != myc) {
                int k1 = k + 1;
                int id = (k1 < row) ? ((k1 << 12) | row) : (rowsh | k1);
                best = min(best, ((unsigned long long)__float_as_uint(d.y) << 24)
                                 | (unsigned long long)id);
            }
            if (c.z != myc) {
                int k2 = k + 2;
                int id = (k2 < row) ? ((k2 << 12) | row) : (rowsh | k2);
                best = min(best, ((unsigned long long)__float_as_uint(d.z) << 24)
                                 | (unsigned long long)id);
            }
            if (c.w != myc) {
                int k3 = k + 3;
                int id = (k3 < row) ? ((k3 << 12) | row) : (rowsh | k3);
                best = min(best, ((unsigned long long)__float_as_uint(d.w) << 24)
                                 | (unsigned long long)id);
            }
        }
        lk = best;
        g_lanebest[mat][row][lane] = lk;
    }
    __syncwarp(0xffffffffu);
    unsigned long long rb = lk;
    #pragma unroll
    for (int o = 16; o > 0; o >>= 1) {
        unsigned long long other = __shfl_xor_sync(0xffffffffu, rb, o);
        rb = min(rb, other);
    }
    if (lane == 0) g_rowbest[mat][row] = rb;
}

// ---------------- Boruvka merge: prefetched, fused cycle-break, slot deaths (d^2) ----------------
__global__ void __launch_bounds__(1024) boruvka_merge() {
    int mat = blockIdx.x;
    if (g_done[mat]) return;

    __shared__ unsigned long long sbest[NPTS];   // 32KB
    __shared__ unsigned short    par[NPTS];      // 8KB
    __shared__ int s_roots;

    int tid = threadIdx.x;

    unsigned long long kreg[4];
    int creg[4];
    #pragma unroll
    for (int j = 0; j < 4; j++) {
        int r = tid + j * 1024;
        kreg[j] = g_rowbest[mat][r];
        creg[j] = g_comp[mat][r];
    }
    #pragma unroll
    for (int j = 0; j < 4; j++) sbest[tid + j * 1024] = INFKEY;
    __syncthreads();

    #pragma unroll
    for (int j = 0; j < 4; j++)
        if (kreg[j] != INFKEY) atomicMin(&sbest[creg[j]], kreg[j]);
    __syncthreads();

    #pragma unroll
    for (int j = 0; j < 4; j++) {
        int c = tid + j * 1024;
        unsigned long long k = sbest[c];
        int p = c;
        if (k != INFKEY) {
            int eid = (int)(k & 0xFFFFFF);
            int u = eid >> 12, v = eid & (NPTS - 1);
            int cu = g_comp[mat][u];
            int d = (cu == c) ? g_comp[mat][v] : cu;
            bool survivor = (sbest[d] == k) && (c < d);   // mutual pair, smaller root wins
            p = survivor ? c : d;
            if (!survivor)
                g_deaths[mat][c] = __uint_as_float((unsigned)(k >> 24));   // d^2
        }
        par[c] = (unsigned short)p;
    }
    __syncthreads();

    for (int it = 0; it < 12; it++) {
        int changed = 0;
        #pragma unroll
        for (int j = 0; j < 4; j++) {
            int c = tid + j * 1024;
            int p = par[c];
            int gp = par[p];
            if (gp != p) { par[c] = (unsigned short)gp; changed = 1; }
        }
        if (!__syncthreads_or(changed)) break;
    }

    if (tid == 0) s_roots = 0;
    __syncthreads();
    int rootcnt = 0;
    #pragma unroll
    for (int j = 0; j < 4; j++) {
        int i = tid + j * 1024;
        int nc = par[creg[j]];
        g_comp[mat][i] = nc;
        rootcnt += (nc == i);
    }
    #pragma unroll
    for (int o = 16; o > 0; o >>= 1) rootcnt += __shfl_xor_sync(0xffffffffu, rootcnt, o);
    if ((tid & 31) == 0 && rootcnt) atomicAdd(&s_roots, rootcnt);
    __syncthreads();
    if (tid == 0 && s_roots <= 1) g_done[mat] = 1;
}

// ---------------- bitonic sort (sqrt at load; warp-local low phases) + fused final loss ----------------
__global__ void __launch_bounds__(1024) sort_kernel(float* __restrict__ out) {
    int mat = blockIdx.x;
    __shared__ float s[NPTS];
    __shared__ float red[1024];
    __shared__ int s_last;
    int tid = threadIdx.x;

    for (int i = tid; i < NPTS; i += 1024)
        s[i] = sqrtf(fmaxf(g_deaths[mat][i], 1e-12f));   // d^2 -> d (identical to R15 values)
    __syncthreads();
    for (int k = 2; k <= NPTS; k <<= 1)
        for (int j2 = k >> 1; j2 > 0; j2 >>= 1) {
            for (int i = tid; i < NPTS; i += 1024) {
                int ixj = i ^ j2;
                if (ixj > i) {
                    float a = s[i], b = s[ixj];
                    bool up = ((i & k) == 0);
                    if ((a > b) == up) { s[i] = b; s[ixj] = a; }
                }
            }
            int next = (j2 > 1) ? (j2 >> 1) : k;   // k-boundary: next distance is k
            if (next >= 32) __syncthreads();
            else            __syncwarp(0xffffffffu);
        }
    __syncthreads();
    for (int i = tid; i < NPTS; i += 1024)
        g_deaths[mat][i] = s[i];

    // ---- last sorted block computes the final loss ----
    __threadfence();
    __syncthreads();
    if (tid == 0) s_last = (atomicAdd(&g_sortcnt, 1) == 1);
    __syncthreads();
    if (!s_last) return;
    __threadfence();
    const float inv = 1.0f / ((float)NPTS * (float)DIM);
    float acc = 0.f;
    for (int i = tid; i < NPTS; i += 1024) {
        float a = g_deaths[0][i], b = g_deaths[1][i];
        acc += fminf(fabsf(a - b), 0.5f * (a + b));
        acc += g_rowdiff[i] * inv;
    }
    red[tid] = acc; __syncthreads();
    #pragma unroll
    for (int st = 512; st > 0; st >>= 1) {
        if (tid < st) red[tid] += red[tid + st];
        __syncthreads();
    }
    if (tid == 0) out[0] = red[0];
}

extern "C" void kernel_launch(void* const* d_in, const int* in_sizes, int n_in,
                              void* d_out, int out_size) {
    const float* x1 = (const float*)d_in[0];
    const float* x2 = (const float*)d_in[1];
    float* out = (float*)d_out;

    cudaFuncSetAttribute(dist_hmma_kernel, cudaFuncAttributeMaxDynamicSharedMemorySize, 65536);

    prep_kernel<<<1024, 256>>>(x1, x2);
    dist_hmma_kernel<<<dim3(528, 1, 2), 256, 65536>>>();
    for (int r = 0; r < 12; r++) {
        boruvka_scan <<<1024, 256>>>();
        boruvka_merge<<<2, 1024>>>();
    }
    sort_kernel<<<2, 1024>>>(out);
}